// round 10
// baseline (speedup 1.0000x reference)
#include <cuda_runtime.h>

#define NPTS     16384
#define THREADS  256
#define CT       8                       // cols per lane (4 packed pairs)
#define RJOB     128                     // rows per block job
#define CJOB     (THREADS * CT)          // 2048 cols per block job
#define NROWJ    (NPTS / RJOB)           // 128
#define NCOLJ    (NPTS / CJOB)           // 8

typedef unsigned long long u64;

// Transformed column (gen) cloud, SoA.
__device__ float g_colx[NPTS], g_coly[NPTS], g_colz[NPTS], g_coln[NPTS];
// Partial mins: plain stores, unique writer per slot -> no init, deterministic.
__device__ float g_rowmin[NCOLJ * NPTS];   // [colj][row]: min over that col-job's cols
__device__ float g_colmin[NROWJ * NPTS];   // [rowj][col]: min over that row-job's rows
__device__ float g_bsum[32];

__device__ __forceinline__ u64 add2(u64 a, u64 b) {
    u64 r; asm("add.rn.f32x2 %0, %1, %2;" : "=l"(r) : "l"(a), "l"(b)); return r;
}
__device__ __forceinline__ u64 fma2(u64 a, u64 b, u64 c) {
    u64 d; asm("fma.rn.f32x2 %0, %1, %2, %3;" : "=l"(d) : "l"(a), "l"(b), "l"(c));
    return d;
}
__device__ __forceinline__ void unpack2(u64 v, float& lo, float& hi) {
    asm("mov.b64 {%0, %1}, %2;" : "=f"(lo), "=f"(hi) : "l"(v));
}

__global__ void prep_kernel(const float* __restrict__ gen) {
    int i = blockIdx.x * blockDim.x + threadIdx.x;
    if (i < NPTS) {
        float x = gen[3 * i], y = gen[3 * i + 1], z = gen[3 * i + 2];
        g_colx[i] = x; g_coly[i] = y; g_colz[i] = z;
        g_coln[i] = fmaf(x, x, fmaf(y, y, z * z));
    }
}

// One block = RJOB rows (gt) x CJOB cols (gen). Each lane owns CT cols in regs
// (data + running col-min); rows stream via smem broadcast. d(a,b) computed ONCE,
// feeding both the row-min (gt->gen) and the col-min (gen->gt).
__global__ __launch_bounds__(THREADS, 3)
void chamfer_kernel(const float* __restrict__ gt) {
    __shared__ __align__(16) float s_row[RJOB][8];     // (-2ax,-2ax,-2ay,-2ay,-2az,-2az,na,na)
    __shared__ float s_rowpart[RJOB][8];               // per-warp row mins

    const int tid  = threadIdx.x;
    const int wid  = tid >> 5;
    const int lane = tid & 31;
    const int rowj = blockIdx.x / NCOLJ;
    const int colj = blockIdx.x % NCOLJ;
    const int r0   = rowj * RJOB;

    // Fill row smem: duplicated-packed so LDS.64 yields broadcast f32x2 pairs.
    for (int r = tid; r < RJOB; r += THREADS) {
        int g = r0 + r;
        float ax = gt[3 * g], ay = gt[3 * g + 1], az = gt[3 * g + 2];
        float na = fmaf(ax, ax, fmaf(ay, ay, az * az));
        s_row[r][0] = -2.0f * ax; s_row[r][1] = -2.0f * ax;
        s_row[r][2] = -2.0f * ay; s_row[r][3] = -2.0f * ay;
        s_row[r][4] = -2.0f * az; s_row[r][5] = -2.0f * az;
        s_row[r][6] = na;         s_row[r][7] = na;
    }

    // Load this lane's CT cols (packed pairs) + init col mins.
    const int c0 = colj * CJOB + tid * CT;
    u64 cbx[4], cby[4], cbz[4], cbn[4];
    {
        const u64* px = (const u64*)(g_colx + c0);
        const u64* py = (const u64*)(g_coly + c0);
        const u64* pz = (const u64*)(g_colz + c0);
        const u64* pn = (const u64*)(g_coln + c0);
        #pragma unroll
        for (int p = 0; p < 4; p++) {
            cbx[p] = px[p]; cby[p] = py[p]; cbz[p] = pz[p]; cbn[p] = pn[p];
        }
    }
    float cm[CT];
    #pragma unroll
    for (int i = 0; i < CT; i++) cm[i] = 3.0e38f;

    __syncthreads();

    #pragma unroll 2
    for (int r = 0; r < RJOB; r++) {
        const u64* rp = (const u64*)s_row[r];
        u64 rx = rp[0], ry = rp[1], rz = rp[2], rn = rp[3];   // broadcast LDS.64
        float rowlane = 3.0e38f;
        #pragma unroll
        for (int p = 0; p < 4; p++) {
            u64 base = add2(cbn[p], rn);                       // |b|^2 + |a|^2 (packed)
            u64 d = fma2(rx, cbx[p], fma2(ry, cby[p], fma2(rz, cbz[p], base)));
            float lo, hi; unpack2(d, lo, hi);
            cm[2 * p]     = fminf(cm[2 * p], lo);              // col mins (regs)
            cm[2 * p + 1] = fminf(cm[2 * p + 1], hi);
            rowlane = fminf(rowlane, fminf(lo, hi));           // row contribution
        }
        // Warp min over 256 cols for this row.
        #pragma unroll
        for (int off = 16; off; off >>= 1)
            rowlane = fminf(rowlane, __shfl_xor_sync(0xFFFFFFFFu, rowlane, off));
        if (lane == 0) s_rowpart[r][wid] = rowlane;
    }
    __syncthreads();

    // Combine 8 warps' row partials; store row-side partial mins.
    for (int r = tid; r < RJOB; r += THREADS) {
        float m = s_rowpart[r][0];
        #pragma unroll
        for (int w = 1; w < 8; w++) m = fminf(m, s_rowpart[r][w]);
        g_rowmin[colj * NPTS + r0 + r] = m;
    }
    // Store col-side partial mins (unique writer per slot).
    float4* dst = (float4*)(g_colmin + rowj * NPTS + c0);
    dst[0] = make_float4(cm[0], cm[1], cm[2], cm[3]);
    dst[1] = make_float4(cm[4], cm[5], cm[6], cm[7]);
}

// 32 blocks x 512 threads = 16384 threads, one point index each.
__global__ __launch_bounds__(512)
void reduce1_kernel() {
    __shared__ float ssum[512];
    int i = blockIdx.x * 512 + threadIdx.x;
    float a = 3.0e38f, b = 3.0e38f;
    #pragma unroll
    for (int j = 0; j < NCOLJ; j++) a = fminf(a, g_rowmin[j * NPTS + i]);
    #pragma unroll 8
    for (int j = 0; j < NROWJ; j++) b = fminf(b, g_colmin[j * NPTS + i]);
    ssum[threadIdx.x] = a + b;
    __syncthreads();
    for (int off = 256; off > 0; off >>= 1) {
        if (threadIdx.x < off) ssum[threadIdx.x] += ssum[threadIdx.x + off];
        __syncthreads();
    }
    if (threadIdx.x == 0) g_bsum[blockIdx.x] = ssum[0];
}

__global__ void reduce2_kernel(float* __restrict__ out) {
    float s = g_bsum[threadIdx.x];
    #pragma unroll
    for (int off = 16; off > 0; off >>= 1)
        s += __shfl_xor_sync(0xFFFFFFFFu, s, off);
    // mean(row mins) + mean(col mins) = (sum of all mins) / NPTS
    if (threadIdx.x == 0) out[0] = s / (float)NPTS;
}

extern "C" void kernel_launch(void* const* d_in, const int* in_sizes, int n_in,
                              void* d_out, int out_size) {
    const float* gt  = (const float*)d_in[0];
    const float* gen = (const float*)d_in[1];
    float* out = (float*)d_out;

    prep_kernel<<<(NPTS + 255) / 256, 256>>>(gen);
    chamfer_kernel<<<NROWJ * NCOLJ, THREADS>>>(gt);
    reduce1_kernel<<<32, 512>>>();
    reduce2_kernel<<<1, 32>>>(out);
}

// round 11
// speedup vs baseline: 1.1263x; 1.1263x over previous
#include <cuda_runtime.h>

#define NPTS     16384
#define THREADS  256
#define CT       8                       // cols per lane (4 packed pairs)
#define RJOB     128                     // rows per block job
#define CJOB     (THREADS * CT)          // 2048 cols per block job
#define NROWJ    (NPTS / RJOB)           // 128
#define NCOLJ    (NPTS / CJOB)           // 8
#define RSTEP    4                       // rows per shfl-tree batch

typedef unsigned long long u64;

// Partial mins: plain stores, unique writer per slot -> no init, deterministic.
__device__ float g_rowmin[NCOLJ * NPTS];   // [colj][row]
__device__ float g_colmin[NROWJ * NPTS];   // [rowj][col]
__device__ float g_bsum[64];

__device__ __forceinline__ u64 pack2f(float lo, float hi) {
    u64 r; asm("mov.b64 %0, {%1, %2};" : "=l"(r) : "f"(lo), "f"(hi)); return r;
}
__device__ __forceinline__ u64 add2(u64 a, u64 b) {
    u64 r; asm("add.rn.f32x2 %0, %1, %2;" : "=l"(r) : "l"(a), "l"(b)); return r;
}
__device__ __forceinline__ u64 fma2(u64 a, u64 b, u64 c) {
    u64 d; asm("fma.rn.f32x2 %0, %1, %2, %3;" : "=l"(d) : "l"(a), "l"(b), "l"(c));
    return d;
}
__device__ __forceinline__ void unpack2(u64 v, float& lo, float& hi) {
    asm("mov.b64 {%0, %1}, %2;" : "=f"(lo), "=f"(hi) : "l"(v));
}

// One block = RJOB rows (gt) x CJOB cols (gen). Each lane owns CT cols in regs
// (data + running col-min); rows stream via smem broadcast. Each pair computed
// ONCE, feeding both the row-min (gt->gen) and the col-min (gen->gt).
__global__ __launch_bounds__(THREADS, 3)
void chamfer_kernel(const float* __restrict__ gt, const float* __restrict__ gen) {
    __shared__ __align__(16) float s_row[RJOB][8];  // (-2ax,-2ax,-2ay,-2ay,-2az,-2az,na,na)
    __shared__ float s_rowpart[RJOB][8];            // per-warp row mins

    const int tid  = threadIdx.x;
    const int wid  = tid >> 5;
    const int lane = tid & 31;
    const int rowj = blockIdx.x / NCOLJ;
    const int colj = blockIdx.x % NCOLJ;
    const int r0   = rowj * RJOB;

    // Fill row smem: duplicated-packed so LDS.64 yields broadcast f32x2 pairs.
    for (int r = tid; r < RJOB; r += THREADS) {
        int g = r0 + r;
        float ax = gt[3 * g], ay = gt[3 * g + 1], az = gt[3 * g + 2];
        float na = fmaf(ax, ax, fmaf(ay, ay, az * az));
        s_row[r][0] = -2.0f * ax; s_row[r][1] = -2.0f * ax;
        s_row[r][2] = -2.0f * ay; s_row[r][3] = -2.0f * ay;
        s_row[r][4] = -2.0f * az; s_row[r][5] = -2.0f * az;
        s_row[r][6] = na;         s_row[r][7] = na;
    }

    // Load + transform this lane's CT cols inline (no prep kernel).
    const int c0 = colj * CJOB + tid * CT;      // 3*c0*4 bytes is 96B-aligned
    float f[24];
    {
        const float4* gp = (const float4*)(gen + 3 * c0);
        #pragma unroll
        for (int v = 0; v < 6; v++) ((float4*)f)[v] = gp[v];
    }
    u64 cbx[4], cby[4], cbz[4], cbn[4];
    #pragma unroll
    for (int p = 0; p < 4; p++) {
        float x0 = f[6 * p],     y0 = f[6 * p + 1], z0 = f[6 * p + 2];
        float x1 = f[6 * p + 3], y1 = f[6 * p + 4], z1 = f[6 * p + 5];
        cbx[p] = pack2f(x0, x1);
        cby[p] = pack2f(y0, y1);
        cbz[p] = pack2f(z0, z1);
        cbn[p] = pack2f(fmaf(x0, x0, fmaf(y0, y0, z0 * z0)),
                        fmaf(x1, x1, fmaf(y1, y1, z1 * z1)));
    }
    float cm[CT];
    #pragma unroll
    for (int i = 0; i < CT; i++) cm[i] = 3.0e38f;

    __syncthreads();

    for (int rb = 0; rb < RJOB; rb += RSTEP) {
        float rl[RSTEP];
        #pragma unroll
        for (int rr = 0; rr < RSTEP; rr++) {
            const u64* rp = (const u64*)s_row[rb + rr];
            u64 rx = rp[0], ry = rp[1], rz = rp[2], rn = rp[3];   // broadcast LDS.64
            float a = 3.0e38f, b = 3.0e38f;                       // 2 row-min chains
            #pragma unroll
            for (int p = 0; p < 4; p++) {
                u64 d = fma2(rx, cbx[p], fma2(ry, cby[p],
                          fma2(rz, cbz[p], add2(cbn[p], rn))));
                float lo, hi; unpack2(d, lo, hi);
                cm[2 * p]     = fminf(cm[2 * p], lo);
                cm[2 * p + 1] = fminf(cm[2 * p + 1], hi);
                a = fminf(a, lo);
                b = fminf(b, hi);
            }
            rl[rr] = fminf(a, b);
        }
        // 4 interleaved warp-min trees (ILP hides SHFL latency).
        #pragma unroll
        for (int off = 16; off; off >>= 1) {
            #pragma unroll
            for (int rr = 0; rr < RSTEP; rr++)
                rl[rr] = fminf(rl[rr], __shfl_xor_sync(0xFFFFFFFFu, rl[rr], off));
        }
        if (lane == 0) {
            #pragma unroll
            for (int rr = 0; rr < RSTEP; rr++) s_rowpart[rb + rr][wid] = rl[rr];
        }
    }
    __syncthreads();

    // Combine 8 warps' row partials; store row-side partial mins.
    for (int r = tid; r < RJOB; r += THREADS) {
        float m = s_rowpart[r][0];
        #pragma unroll
        for (int w = 1; w < 8; w++) m = fminf(m, s_rowpart[r][w]);
        g_rowmin[colj * NPTS + r0 + r] = m;
    }
    // Store col-side partial mins (unique writer per slot).
    float4* dst = (float4*)(g_colmin + rowj * NPTS + c0);
    dst[0] = make_float4(cm[0], cm[1], cm[2], cm[3]);
    dst[1] = make_float4(cm[4], cm[5], cm[6], cm[7]);
}

// 64 blocks x 512 threads: blocks 0..31 reduce the row side (8 partials/point),
// blocks 32..63 the col side (128 partials/point). Coalesced across lanes.
__global__ __launch_bounds__(512)
void reduce1_kernel() {
    __shared__ float ssum[512];
    float m = 3.0e38f;
    if (blockIdx.x < 32) {
        int i = blockIdx.x * 512 + threadIdx.x;
        #pragma unroll
        for (int j = 0; j < NCOLJ; j++) m = fminf(m, g_rowmin[j * NPTS + i]);
    } else {
        int i = (blockIdx.x - 32) * 512 + threadIdx.x;
        #pragma unroll 8
        for (int j = 0; j < NROWJ; j++) m = fminf(m, g_colmin[j * NPTS + i]);
    }
    ssum[threadIdx.x] = m;
    __syncthreads();
    for (int off = 256; off > 0; off >>= 1) {
        if (threadIdx.x < off) ssum[threadIdx.x] += ssum[threadIdx.x + off];
        __syncthreads();
    }
    if (threadIdx.x == 0) g_bsum[blockIdx.x] = ssum[0];
}

__global__ void reduce2_kernel(float* __restrict__ out) {
    float s = g_bsum[threadIdx.x] + g_bsum[threadIdx.x + 32];
    #pragma unroll
    for (int off = 16; off > 0; off >>= 1)
        s += __shfl_xor_sync(0xFFFFFFFFu, s, off);
    // mean(row mins) + mean(col mins) = (sum of all mins) / NPTS
    if (threadIdx.x == 0) out[0] = s / (float)NPTS;
}

extern "C" void kernel_launch(void* const* d_in, const int* in_sizes, int n_in,
                              void* d_out, int out_size) {
    const float* gt  = (const float*)d_in[0];
    const float* gen = (const float*)d_in[1];
    float* out = (float*)d_out;

    chamfer_kernel<<<NROWJ * NCOLJ, THREADS>>>(gt, gen);
    reduce1_kernel<<<64, 512>>>();
    reduce2_kernel<<<1, 32>>>(out);
}